// round 1
// baseline (speedup 1.0000x reference)
#include <cuda_runtime.h>
#include <math.h>

// Problem constants
#define BB 8
#define NN_SEQ 2048
#define DD 512

// GEMM tile config
#define BM 128
#define BN 128
#define BK 8
#define TM 8
#define TN 8
#define NTHREADS 256

// Scratch (device globals: allocation-free)
__device__ float g_q[BB * NN_SEQ * DD];     // 32 MB
__device__ float g_v[BB * NN_SEQ * DD];     // 32 MB
__device__ float g_s[(size_t)BB * NN_SEQ * NN_SEQ]; // 128 MB
__device__ float g_h[BB * NN_SEQ * DD];     // 32 MB

// C[M,N] = alpha * A[M,K] @ op(B) + bias
//   TRANSB=true : op(B) = B^T with B stored [N,K] row-major (C[m,n] = sum_k A[m,k]*B[n,k])
//   TRANSB=false: op(B) = B   with B stored [K,N] row-major
// Assumes M%BM==0, N%BN==0, K%BK==0 (true for all shapes here).
template <bool TRANSB, bool HASBIAS>
__global__ __launch_bounds__(NTHREADS)
void gemm_kernel(const float* __restrict__ A, const float* __restrict__ Bm,
                 const float* __restrict__ bias, float* __restrict__ C,
                 int M, int N, int K, float alpha,
                 long strideA, long strideB, long strideC)
{
    const int batch = blockIdx.z;
    A  += (long)batch * strideA;
    Bm += (long)batch * strideB;
    C  += (long)batch * strideC;

    __shared__ float As[BK][BM + 4];
    __shared__ float Bs[BK][BN + 4];

    const int tid = threadIdx.x;
    const int tx = tid & 15;          // 0..15 -> col group
    const int ty = tid >> 4;          // 0..15 -> row group

    const int rowBase = blockIdx.y * BM;
    const int colBase = blockIdx.x * BN;

    // A-tile loader: 128 rows x 8 k; thread -> (rowA, kA group of 4)
    const int rowA = tid >> 1;          // 0..127
    const int kA   = (tid & 1) * 4;     // 0 or 4

    // B-tile loader for NN: 8 k-rows x 128 n
    const int kB = tid >> 5;            // 0..7
    const int cB = (tid & 31) * 4;      // 0..124

    float acc[TM][TN] = {};

    for (int k0 = 0; k0 < K; k0 += BK) {
        // Load A tile (transposed into smem)
        {
            float4 a4 = *reinterpret_cast<const float4*>(
                &A[(long)(rowBase + rowA) * K + (k0 + kA)]);
            As[kA + 0][rowA] = a4.x;
            As[kA + 1][rowA] = a4.y;
            As[kA + 2][rowA] = a4.z;
            As[kA + 3][rowA] = a4.w;
        }
        // Load B tile
        if (TRANSB) {
            float4 b4 = *reinterpret_cast<const float4*>(
                &Bm[(long)(colBase + rowA) * K + (k0 + kA)]);
            Bs[kA + 0][rowA] = b4.x;
            Bs[kA + 1][rowA] = b4.y;
            Bs[kA + 2][rowA] = b4.z;
            Bs[kA + 3][rowA] = b4.w;
        } else {
            float4 b4 = *reinterpret_cast<const float4*>(
                &Bm[(long)(k0 + kB) * N + (colBase + cB)]);
            *reinterpret_cast<float4*>(&Bs[kB][cB]) = b4;
        }
        __syncthreads();

        #pragma unroll
        for (int k = 0; k < BK; k++) {
            float a[TM], b[TN];
            #pragma unroll
            for (int i = 0; i < TM; i++) a[i] = As[k][ty * TM + i];
            #pragma unroll
            for (int j = 0; j < TN; j++) b[j] = Bs[k][tx * TN + j];
            #pragma unroll
            for (int i = 0; i < TM; i++)
                #pragma unroll
                for (int j = 0; j < TN; j++)
                    acc[i][j] = fmaf(a[i], b[j], acc[i][j]);
        }
        __syncthreads();
    }

    // Epilogue: scale (+bias), vectorized stores
    #pragma unroll
    for (int i = 0; i < TM; i++) {
        const long crow = (long)(rowBase + ty * TM + i) * N + colBase + tx * TN;
        #pragma unroll
        for (int jv = 0; jv < TN; jv += 4) {
            float4 o;
            float* po = &o.x;
            #pragma unroll
            for (int j = 0; j < 4; j++) {
                float val = acc[i][jv + j] * alpha;
                if (HASBIAS) val += bias[colBase + tx * TN + jv + j];
                po[j] = val;
            }
            *reinterpret_cast<float4*>(&C[crow + jv]) = o;
        }
    }
}

// Row-wise softmax in place. One block per row of length n.
__global__ __launch_bounds__(256)
void softmax_kernel(float* __restrict__ s, int n)
{
    float* row = s + (long)blockIdx.x * n;
    const int tid = threadIdx.x;
    __shared__ float red[256];

    float m = -INFINITY;
    for (int i = tid; i < n; i += 256) m = fmaxf(m, row[i]);
    red[tid] = m;
    __syncthreads();
    for (int off = 128; off > 0; off >>= 1) {
        if (tid < off) red[tid] = fmaxf(red[tid], red[tid + off]);
        __syncthreads();
    }
    m = red[0];
    __syncthreads();

    float sum = 0.f;
    for (int i = tid; i < n; i += 256) {
        float e = __expf(row[i] - m);
        row[i] = e;
        sum += e;
    }
    red[tid] = sum;
    __syncthreads();
    for (int off = 128; off > 0; off >>= 1) {
        if (tid < off) red[tid] += red[tid + off];
        __syncthreads();
    }
    const float inv = 1.f / red[0];
    __syncthreads();

    for (int i = tid; i < n; i += 256) row[i] *= inv;
}

extern "C" void kernel_launch(void* const* d_in, const int* in_sizes, int n_in,
                              void* d_out, int out_size)
{
    (void)in_sizes; (void)n_in; (void)out_size;
    const float* query   = (const float*)d_in[0];
    const float* context = (const float*)d_in[1];
    const float* Wq      = (const float*)d_in[2];
    const float* bq      = (const float*)d_in[3];
    const float* Wv      = (const float*)d_in[4];
    const float* bv      = (const float*)d_in[5];
    const float* Wo      = (const float*)d_in[6];
    const float* bo      = (const float*)d_in[7];
    float* out = (float*)d_out;

    float *q, *v, *s, *h;
    cudaGetSymbolAddress((void**)&q, g_q);
    cudaGetSymbolAddress((void**)&v, g_v);
    cudaGetSymbolAddress((void**)&s, g_s);
    cudaGetSymbolAddress((void**)&h, g_h);

    const float scale = 1.0f / sqrtf((float)DD);
    const int M_flat = BB * NN_SEQ; // 16384

    // 1) q = query @ Wq^T + bq   (M=16384, N=512, K=512)
    {
        dim3 grid(DD / BN, M_flat / BM, 1);
        gemm_kernel<true, true><<<grid, NTHREADS>>>(
            query, Wq, bq, q, M_flat, DD, DD, 1.0f, 0, 0, 0);
    }
    // 2) v = context @ Wv^T + bv
    {
        dim3 grid(DD / BN, M_flat / BM, 1);
        gemm_kernel<true, true><<<grid, NTHREADS>>>(
            context, Wv, bv, v, M_flat, DD, DD, 1.0f, 0, 0, 0);
    }
    // 3) scores = scale * q @ context^T  (batched: M=N=2048, K=512)
    {
        dim3 grid(NN_SEQ / BN, NN_SEQ / BM, BB);
        gemm_kernel<true, false><<<grid, NTHREADS>>>(
            q, context, nullptr, s, NN_SEQ, NN_SEQ, DD, scale,
            (long)NN_SEQ * DD, (long)NN_SEQ * DD, (long)NN_SEQ * NN_SEQ);
    }
    // 4) softmax rows
    softmax_kernel<<<BB * NN_SEQ, 256>>>(s, NN_SEQ);

    // 5) h = attn @ v  (batched NN: M=2048, N=512, K=2048)
    {
        dim3 grid(DD / BN, NN_SEQ / BM, BB);
        gemm_kernel<false, false><<<grid, NTHREADS>>>(
            s, v, nullptr, h, NN_SEQ, DD, NN_SEQ, 1.0f,
            (long)NN_SEQ * NN_SEQ, (long)NN_SEQ * DD, (long)NN_SEQ * DD);
    }
    // 6) out = h @ Wo^T + bo
    {
        dim3 grid(DD / BN, M_flat / BM, 1);
        gemm_kernel<true, true><<<grid, NTHREADS>>>(
            h, Wo, bo, out, M_flat, DD, DD, 1.0f, 0, 0, 0);
    }
}

// round 4
// speedup vs baseline: 2.7988x; 2.7988x over previous
#include <cuda_runtime.h>
#include <cuda_bf16.h>
#include <cstdint>
#include <math.h>

#define BB 8
#define NSEQ 2048
#define DDIM 512
#define MFLAT (BB*NSEQ)

// ---------------- scratch (device globals: allocation-free) ----------------
__device__ __nv_bfloat16 g_qry_hi[MFLAT*DDIM], g_qry_lo[MFLAT*DDIM];
__device__ __nv_bfloat16 g_ctx_hi[MFLAT*DDIM], g_ctx_lo[MFLAT*DDIM];
__device__ __nv_bfloat16 g_wq_hi[DDIM*DDIM],  g_wq_lo[DDIM*DDIM];
__device__ __nv_bfloat16 g_wv_hi[DDIM*DDIM],  g_wv_lo[DDIM*DDIM];
__device__ __nv_bfloat16 g_wo_hi[DDIM*DDIM],  g_wo_lo[DDIM*DDIM];
__device__ __nv_bfloat16 g_q_hi[MFLAT*DDIM],  g_q_lo[MFLAT*DDIM];
__device__ __nv_bfloat16 g_vT_hi[MFLAT*DDIM], g_vT_lo[MFLAT*DDIM];
__device__ float         g_s[(size_t)BB*NSEQ*NSEQ];
__device__ __nv_bfloat16 g_attn_hi[(size_t)BB*NSEQ*NSEQ], g_attn_lo[(size_t)BB*NSEQ*NSEQ];
__device__ __nv_bfloat16 g_h_hi[MFLAT*DDIM],  g_h_lo[MFLAT*DDIM];

// ---------------- helpers ----------------
__device__ __forceinline__ uint32_t smem_u32(const void* p){
    uint32_t a;
    asm("{ .reg .u64 t; cvta.to.shared.u64 t, %1; cvt.u32.u64 %0, t; }" : "=r"(a) : "l"(p));
    return a;
}
__device__ __forceinline__ void split2(float v, __nv_bfloat16& h, __nv_bfloat16& l){
    h = __float2bfloat16(v);
    l = __float2bfloat16(v - __bfloat162float(h));
}

#define CP_ASYNC16(sm, gm) \
    asm volatile("cp.async.cg.shared.global [%0], [%1], 16;" :: "r"(sm), "l"(gm))
#define CP_COMMIT() asm volatile("cp.async.commit_group;" ::: "memory")
#define CP_WAIT1()  asm volatile("cp.async.wait_group 1;" ::: "memory")
#define CP_WAIT0()  asm volatile("cp.async.wait_group 0;" ::: "memory")

__device__ __forceinline__ void ldmatrix_x4(uint32_t& r0, uint32_t& r1, uint32_t& r2, uint32_t& r3, uint32_t addr){
    asm volatile("ldmatrix.sync.aligned.m8n8.x4.shared.b16 {%0,%1,%2,%3}, [%4];"
        : "=r"(r0), "=r"(r1), "=r"(r2), "=r"(r3) : "r"(addr));
}
__device__ __forceinline__ void ldmatrix_x2(uint32_t& r0, uint32_t& r1, uint32_t addr){
    asm volatile("ldmatrix.sync.aligned.m8n8.x2.shared.b16 {%0,%1}, [%2];"
        : "=r"(r0), "=r"(r1) : "r"(addr));
}
__device__ __forceinline__ void mma_bf16(float* c, const uint32_t* a, const uint32_t* b){
    asm volatile(
        "mma.sync.aligned.m16n8k16.row.col.f32.bf16.bf16.f32 "
        "{%0,%1,%2,%3}, {%4,%5,%6,%7}, {%8,%9}, {%0,%1,%2,%3};"
        : "+f"(c[0]), "+f"(c[1]), "+f"(c[2]), "+f"(c[3])
        : "r"(a[0]), "r"(a[1]), "r"(a[2]), "r"(a[3]), "r"(b[0]), "r"(b[1]));
}

// ---------------- HMMA GEMM ----------------
// C[128x128 tile] = alpha * sum over 3 segments of Aseg[M,K] @ Bseg[N,K]^T (+ bias)
// Segments: (Ahi,Bhi), (Ahi,Blo), (Alo,Bhi)  -> split-bf16 fp32 emulation.
// MODE 0: fp32 out. MODE 1: split bf16 out. MODE 2: split bf16 out, transposed
//         per-batch (v^T layout [DDIM, NSEQ]); requires N==DDIM, flat M, z==1.
// Smem tile: 128 rows x 32 k of bf16, row pitch 80B (64B data + 16B pad) ->
// conflict-free ldmatrix (banks 20*r mod 32 distinct over any 8 rows).
#define PITCH 80
#define TILEB (128*PITCH)

template<int MODE>
__global__ __launch_bounds__(256)
void mma_gemm(const __nv_bfloat16* __restrict__ Ahi, const __nv_bfloat16* __restrict__ Alo,
              const __nv_bfloat16* __restrict__ Bhi, const __nv_bfloat16* __restrict__ Blo,
              const float* __restrict__ bias,
              float* __restrict__ outF, __nv_bfloat16* __restrict__ outHi, __nv_bfloat16* __restrict__ outLo,
              int M, int N, int K, float alpha,
              long sA, long sB, long sC)
{
    __shared__ __align__(128) char smem[2][2*TILEB];  // per buf: A tile then B tile

    const int tid  = threadIdx.x;
    const int warp = tid >> 5;
    const int lane = tid & 31;
    const int warpM = warp >> 2;   // 0..1  (64 rows each)
    const int warpN = warp & 3;    // 0..3  (32 cols each)

    const int z = blockIdx.z;
    Ahi += (long)z * sA;  Alo += (long)z * sA;
    Bhi += (long)z * sB;  Blo += (long)z * sB;
    if (MODE == 0) { outF += (long)z * sC; }
    else { outHi += (long)z * sC; outLo += (long)z * sC; }

    const int rowBase = blockIdx.y * 128;
    const int colBase = blockIdx.x * 128;

    const uint32_t smBase = smem_u32(&smem[0][0]);

    const __nv_bfloat16* Aseg[3] = {Ahi, Ahi, Alo};
    const __nv_bfloat16* Bseg[3] = {Bhi, Blo, Bhi};
    const int tps = K >> 5;        // 32-k tiles per segment
    const int T = 3 * tps;

    // global->smem loader mapping: 2 threads per row, 32B each
    const int ldRow = tid >> 1;
    const int ldOff = (tid & 1) * 32;   // byte offset within 64B row

    auto issue = [&](int t){
        const int b = t & 1;
        const int seg = t / tps;
        const int kk  = (t - seg * tps) << 5;   // element offset
        const __nv_bfloat16* Ap = Aseg[seg] + (long)(rowBase + ldRow) * K + kk + (ldOff >> 1);
        const __nv_bfloat16* Bp = Bseg[seg] + (long)(colBase + ldRow) * K + kk + (ldOff >> 1);
        const uint32_t sa = smBase + b * (2*TILEB) + ldRow * PITCH + ldOff;
        const uint32_t sb = sa + TILEB;
        CP_ASYNC16(sa,      Ap);
        CP_ASYNC16(sa + 16, Ap + 8);
        CP_ASYNC16(sb,      Bp);
        CP_ASYNC16(sb + 16, Bp + 8);
        CP_COMMIT();
    };

    float acc[4][4][4];
    #pragma unroll
    for (int i = 0; i < 4; i++)
        #pragma unroll
        for (int j = 0; j < 4; j++)
            #pragma unroll
            for (int c = 0; c < 4; c++) acc[i][j][c] = 0.f;

    issue(0);

    for (int t = 0; t < T; t++) {
        if (t + 1 < T) { issue(t + 1); CP_WAIT1(); } else { CP_WAIT0(); }
        __syncthreads();

        const int b = t & 1;
        const uint32_t aBase = smBase + b * (2*TILEB);
        const uint32_t bBase = aBase + TILEB;
        // ldmatrix lane addresses
        const uint32_t aAddr0 = aBase + (warpM*64 + (lane & 15)) * PITCH + ((lane >> 4) & 1) * 16;
        const uint32_t bAddr0 = bBase + (warpN*32 + (lane & 7))  * PITCH + ((lane >> 3) & 1) * 16;

        #pragma unroll
        for (int ks = 0; ks < 2; ks++) {
            const uint32_t kByte = ks * 32;
            uint32_t afr[4][4];
            #pragma unroll
            for (int mt = 0; mt < 4; mt++)
                ldmatrix_x4(afr[mt][0], afr[mt][1], afr[mt][2], afr[mt][3],
                            aAddr0 + mt * 16 * PITCH + kByte);
            uint32_t bfr[4][2];
            #pragma unroll
            for (int nt = 0; nt < 4; nt++)
                ldmatrix_x2(bfr[nt][0], bfr[nt][1],
                            bAddr0 + nt * 8 * PITCH + kByte);
            #pragma unroll
            for (int mt = 0; mt < 4; mt++)
                #pragma unroll
                for (int nt = 0; nt < 4; nt++)
                    mma_bf16(acc[mt][nt], afr[mt], bfr[nt]);
        }
        __syncthreads();
    }

    // ---------------- epilogue (registers -> gmem) ----------------
    #pragma unroll
    for (int mt = 0; mt < 4; mt++) {
        const int r0 = rowBase + warpM*64 + mt*16 + (lane >> 2);
        #pragma unroll
        for (int nt = 0; nt < 4; nt++) {
            const int gc = colBase + warpN*32 + nt*8 + (lane & 3)*2;
            float v00 = acc[mt][nt][0] * alpha;
            float v01 = acc[mt][nt][1] * alpha;
            float v10 = acc[mt][nt][2] * alpha;
            float v11 = acc[mt][nt][3] * alpha;
            if (bias) {
                const float b0 = bias[gc], b1 = bias[gc+1];
                v00 += b0; v01 += b1; v10 += b0; v11 += b1;
            }
            if (MODE == 0) {
                *(float2*)&outF[(long)r0 * N + gc]       = make_float2(v00, v01);
                *(float2*)&outF[(long)(r0+8) * N + gc]   = make_float2(v10, v11);
            } else if (MODE == 1) {
                __nv_bfloat162 h, l;
                split2(v00, h.x, l.x); split2(v01, h.y, l.y);
                *(__nv_bfloat162*)&outHi[(long)r0 * N + gc] = h;
                *(__nv_bfloat162*)&outLo[(long)r0 * N + gc] = l;
                split2(v10, h.x, l.x); split2(v11, h.y, l.y);
                *(__nv_bfloat162*)&outHi[(long)(r0+8) * N + gc] = h;
                *(__nv_bfloat162*)&outLo[(long)(r0+8) * N + gc] = l;
            } else { // MODE 2: v^T per batch [DDIM, NSEQ]
                const int rows[2] = {r0, r0 + 8};
                const float vals[2][2] = {{v00, v01}, {v10, v11}};
                #pragma unroll
                for (int rr = 0; rr < 2; rr++) {
                    const int bb = rows[rr] >> 11, tok = rows[rr] & 2047;
                    const long base = (long)bb * (DDIM * NSEQ) + tok;
                    #pragma unroll
                    for (int cc = 0; cc < 2; cc++) {
                        __nv_bfloat16 h, l; split2(vals[rr][cc], h, l);
                        const long idx = base + (long)(gc + cc) * NSEQ;
                        outHi[idx] = h;
                        outLo[idx] = l;
                    }
                }
            }
        }
    }
}

// ---------------- fp32 -> (bf16 hi, bf16 lo) ----------------
__global__ __launch_bounds__(256)
void split_kernel(const float* __restrict__ x, __nv_bfloat16* __restrict__ hi,
                  __nv_bfloat16* __restrict__ lo, int n4)
{
    const int i = blockIdx.x * blockDim.x + threadIdx.x;
    if (i >= n4) return;
    float4 v = ((const float4*)x)[i];
    __nv_bfloat162 h0, h1, l0, l1;
    split2(v.x, h0.x, l0.x); split2(v.y, h0.y, l0.y);
    split2(v.z, h1.x, l1.x); split2(v.w, h1.y, l1.y);
    ((__nv_bfloat162*)hi)[2*i]   = h0;
    ((__nv_bfloat162*)hi)[2*i+1] = h1;
    ((__nv_bfloat162*)lo)[2*i]   = l0;
    ((__nv_bfloat162*)lo)[2*i+1] = l1;
}

// ---------------- softmax + split ----------------
__global__ __launch_bounds__(256)
void softmax_split_kernel(float* __restrict__ s, __nv_bfloat16* __restrict__ hi,
                          __nv_bfloat16* __restrict__ lo, int n)
{
    const long rbase = (long)blockIdx.x * n;
    float* row = s + rbase;
    const int tid = threadIdx.x;
    __shared__ float red[256];

    float m = -INFINITY;
    for (int i = tid; i < n; i += 256) m = fmaxf(m, row[i]);
    red[tid] = m; __syncthreads();
    for (int off = 128; off > 0; off >>= 1) {
        if (tid < off) red[tid] = fmaxf(red[tid], red[tid + off]);
        __syncthreads();
    }
    m = red[0]; __syncthreads();

    float sum = 0.f;
    for (int i = tid; i < n; i += 256) {
        float e = __expf(row[i] - m);
        row[i] = e;
        sum += e;
    }
    red[tid] = sum; __syncthreads();
    for (int off = 128; off > 0; off >>= 1) {
        if (tid < off) red[tid] += red[tid + off];
        __syncthreads();
    }
    const float inv = 1.f / red[0];
    __syncthreads();

    for (int i = tid; i < n; i += 256) {
        float v = row[i] * inv;
        __nv_bfloat16 h, l; split2(v, h, l);
        hi[rbase + i] = h;
        lo[rbase + i] = l;
    }
}

// ---------------- launch ----------------
extern "C" void kernel_launch(void* const* d_in, const int* in_sizes, int n_in,
                              void* d_out, int out_size)
{
    (void)in_sizes; (void)n_in; (void)out_size;
    const float* query   = (const float*)d_in[0];
    const float* context = (const float*)d_in[1];
    const float* Wq      = (const float*)d_in[2];
    const float* bq      = (const float*)d_in[3];
    const float* Wv      = (const float*)d_in[4];
    const float* bv      = (const float*)d_in[5];
    const float* Wo      = (const float*)d_in[6];
    const float* bo      = (const float*)d_in[7];
    float* out = (float*)d_out;

    __nv_bfloat16 *qry_hi,*qry_lo,*ctx_hi,*ctx_lo,*wq_hi,*wq_lo,*wv_hi,*wv_lo,*wo_hi,*wo_lo;
    __nv_bfloat16 *q_hi,*q_lo,*vT_hi,*vT_lo,*attn_hi,*attn_lo,*h_hi,*h_lo;
    float* s;
    cudaGetSymbolAddress((void**)&qry_hi, g_qry_hi);  cudaGetSymbolAddress((void**)&qry_lo, g_qry_lo);
    cudaGetSymbolAddress((void**)&ctx_hi, g_ctx_hi);  cudaGetSymbolAddress((void**)&ctx_lo, g_ctx_lo);
    cudaGetSymbolAddress((void**)&wq_hi,  g_wq_hi);   cudaGetSymbolAddress((void**)&wq_lo,  g_wq_lo);
    cudaGetSymbolAddress((void**)&wv_hi,  g_wv_hi);   cudaGetSymbolAddress((void**)&wv_lo,  g_wv_lo);
    cudaGetSymbolAddress((void**)&wo_hi,  g_wo_hi);   cudaGetSymbolAddress((void**)&wo_lo,  g_wo_lo);
    cudaGetSymbolAddress((void**)&q_hi,   g_q_hi);    cudaGetSymbolAddress((void**)&q_lo,   g_q_lo);
    cudaGetSymbolAddress((void**)&vT_hi,  g_vT_hi);   cudaGetSymbolAddress((void**)&vT_lo,  g_vT_lo);
    cudaGetSymbolAddress((void**)&attn_hi,g_attn_hi); cudaGetSymbolAddress((void**)&attn_lo,g_attn_lo);
    cudaGetSymbolAddress((void**)&h_hi,   g_h_hi);    cudaGetSymbolAddress((void**)&h_lo,   g_h_lo);
    cudaGetSymbolAddress((void**)&s,      g_s);

    const float scale = 1.0f / sqrtf((float)DDIM);

    // split inputs
    {
        int n4 = (MFLAT * DDIM) / 4;
        split_kernel<<<(n4 + 255) / 256, 256>>>(query,   qry_hi, qry_lo, n4);
        split_kernel<<<(n4 + 255) / 256, 256>>>(context, ctx_hi, ctx_lo, n4);
        int w4 = (DDIM * DDIM) / 4;
        split_kernel<<<(w4 + 255) / 256, 256>>>(Wq, wq_hi, wq_lo, w4);
        split_kernel<<<(w4 + 255) / 256, 256>>>(Wv, wv_hi, wv_lo, w4);
        split_kernel<<<(w4 + 255) / 256, 256>>>(Wo, wo_hi, wo_lo, w4);
    }

    // 1) q = query @ Wq^T + bq  -> split q
    mma_gemm<1><<<dim3(DDIM/128, MFLAT/128, 1), 256>>>(
        qry_hi, qry_lo, wq_hi, wq_lo, bq, nullptr, q_hi, q_lo,
        MFLAT, DDIM, DDIM, 1.0f, 0, 0, 0);

    // 2) v = context @ Wv^T + bv -> split v^T (per batch [DDIM, NSEQ])
    mma_gemm<2><<<dim3(DDIM/128, MFLAT/128, 1), 256>>>(
        ctx_hi, ctx_lo, wv_hi, wv_lo, bv, nullptr, vT_hi, vT_lo,
        MFLAT, DDIM, DDIM, 1.0f, 0, 0, 0);

    // 3) scores = scale * q @ context^T  (batched) -> fp32 s
    mma_gemm<0><<<dim3(NSEQ/128, NSEQ/128, BB), 256>>>(
        q_hi, q_lo, ctx_hi, ctx_lo, nullptr, s, nullptr, nullptr,
        NSEQ, NSEQ, DDIM, scale,
        (long)NSEQ * DDIM, (long)NSEQ * DDIM, (long)NSEQ * NSEQ);

    // 4) softmax rows -> split attn
    softmax_split_kernel<<<BB * NSEQ, 256>>>(s, attn_hi, attn_lo, NSEQ);

    // 5) h = attn @ v = attn @ (v^T)^T  (batched) -> split h
    mma_gemm<1><<<dim3(DDIM/128, NSEQ/128, BB), 256>>>(
        attn_hi, attn_lo, vT_hi, vT_lo, nullptr, nullptr, h_hi, h_lo,
        NSEQ, DDIM, NSEQ, 1.0f,
        (long)NSEQ * NSEQ, (long)DDIM * NSEQ, (long)NSEQ * DDIM);

    // 6) out = h @ Wo^T + bo -> fp32
    mma_gemm<0><<<dim3(DDIM/128, MFLAT/128, 1), 256>>>(
        h_hi, h_lo, wo_hi, wo_lo, bo, out, nullptr, nullptr,
        MFLAT, DDIM, DDIM, 1.0f, 0, 0, 0);
}